// round 16
// baseline (speedup 1.0000x reference)
#include <cuda_runtime.h>
#include <cuda_fp16.h>
#include <mma.h>
using namespace nvcuda;

// Problem constants
#define Bsz  2
#define Cc   64
#define Hh   128
#define Ww   256
#define HG   122880          // grid rows = L*KH
#define LOUT 40960           // output rows after stride-3 depthwise
#define TL   16              // output rows per block (sampler)
#define NR   (3*TL + 2)      // local sampled rows incl. +/-1 halo  (50)
#define NP   (NR * 3)        // local sampled points (150)
#define VROW 36              // v_sm2 row pitch in half2 (144B)
#define LTI  128             // pw_k l-tile

__device__ __half g_xT[Bsz * Hh * Ww * Cc];        // x as [B,H,W,C] fp16
__device__ __half g_z[Bsz * LOUT * Cc];            // depthwise output [b*l][c] fp16

// ---------------------------------------------------------------------------
// Kernel 1: NCHW fp32 -> NHWC fp16 transpose.
// One block per (b,h): stage [w][c] in smem, write 128B channel vectors.
// ---------------------------------------------------------------------------
__global__ __launch_bounds__(256) void transpose_k(const float* __restrict__ x) {
    __shared__ __half s2[256][72];     // 36864 B, pitch 72 halves (16B-aligned rows)
    const int bh = blockIdx.x;         // b*128 + h
    const int b  = bh >> 7;
    const int t  = threadIdx.x;        // = w

    const float* __restrict__ xr = x + ((size_t)b * Cc * Hh + (bh & 127)) * Ww + t;
#pragma unroll 8
    for (int c = 0; c < 64; c++)
        s2[t][c] = __float2half_rn(xr[(size_t)c * (Hh * Ww)]);
    __syncthreads();

    uint4* dst = (uint4*)&g_xT[((size_t)bh * Ww + t) * Cc];
    const uint4* src = (const uint4*)&s2[t][0];
#pragma unroll
    for (int k = 0; k < 8; k++) dst[k] = src[k];   // 8 x 16B = full 64-ch row
}

// ---------------------------------------------------------------------------
// Kernel 2: grid_sample + spatial attention + depthwise(s=3) -> g_z (fp16)
// grid: (LOUT/TL, B), block 256. Branch-free clamped gather, 16 lanes/point.
// ---------------------------------------------------------------------------
__global__ __launch_bounds__(256) void sample_k(
    const float* __restrict__ grid,
    const float* __restrict__ sa_w, const float* __restrict__ sa_b,
    const float* __restrict__ dw_w, const float* __restrict__ dw_b)
{
    __shared__ __align__(16) __half2 v_sm2[NP * VROW]; // 21600 B sampled vecs
    __shared__ __align__(16) float4 cw_sm[NP];         // per-tap weights (0 if OOB)
    __shared__ unsigned cxy_sm[NP];                    // packed clamped coords
    __shared__ float savg[NP];
    __shared__ float smax_[NP];
    __shared__ float m_att[TL * 3 * 3];                // (1 + sigmoid) gates
    __shared__ float dw_sm[64 * 9];

    const int t  = threadIdx.x;
    const int b  = blockIdx.y;
    const int l0 = blockIdx.x * TL;
    const __half* __restrict__ xb = g_xT + (size_t)b * (Hh * Ww * Cc);

    // ---- Stage 0: dw weights + per-point coordinate precompute -------------
    for (int i = t; i < 576; i += 256)
        dw_sm[i] = dw_w[i];

    if (t < NP) {
        float4 w4 = make_float4(0.f, 0.f, 0.f, 0.f);
        int xc0 = 0, xc1 = 0, yc0 = 0, yc1 = 0;
        int gidx = (3 * l0 - 1) * 3 + t;              // linear grid point index
        if (gidx >= 0 && gidx < HG * 3) {
            float2 g2 = __ldg((const float2*)grid + gidx);
            float gx = (g2.x + 1.0f) * 128.0f - 0.5f;   // W/2
            float gy = (g2.y + 1.0f) * 64.0f  - 0.5f;   // H/2
            float x0f = floorf(gx), y0f = floorf(gy);
            float wx = gx - x0f, wy = gy - y0f;
            int x0 = (int)x0f, y0 = (int)y0f;
            float vx0 = ((unsigned)x0       < (unsigned)Ww) ? 1.f : 0.f;
            float vx1 = ((unsigned)(x0 + 1) < (unsigned)Ww) ? 1.f : 0.f;
            float vy0 = ((unsigned)y0       < (unsigned)Hh) ? 1.f : 0.f;
            float vy1 = ((unsigned)(y0 + 1) < (unsigned)Hh) ? 1.f : 0.f;
            w4.x = (1.f - wx) * (1.f - wy) * vx0 * vy0;  // w00
            w4.y = wx * (1.f - wy)         * vx1 * vy0;  // w10
            w4.z = (1.f - wx) * wy         * vx0 * vy1;  // w01
            w4.w = wx * wy                 * vx1 * vy1;  // w11
            xc0 = min(max(x0, 0), Ww - 1);
            xc1 = min(max(x0 + 1, 0), Ww - 1);
            yc0 = min(max(y0, 0), Hh - 1);
            yc1 = min(max(y0 + 1, 0), Hh - 1);
        }
        cw_sm[t] = w4;
        cxy_sm[t] = (unsigned)xc0 | ((unsigned)xc1 << 8)
                  | ((unsigned)yc0 << 16) | ((unsigned)yc1 << 24);
    }
    __syncthreads();

    // ---- Stage 1: branch-free bilinear gather, 16 lanes/pt, 4 ch/lane ------
    const int grp  = t >> 4;      // 0..15
    const int lane = t & 15;
    const int co   = lane * 4;    // channel offset (halves)
    const __half* __restrict__ xc = xb + co;

    for (int p = grp; p < NP; p += 16) {
        float4 w4 = cw_sm[p];
        unsigned pk = cxy_sm[p];
        int xc0 = pk & 255, xc1 = (pk >> 8) & 255;
        int yc0 = (pk >> 16) & 255, yc1 = pk >> 24;
        uint2 u0 = *(const uint2*)(xc + (yc0 * Ww + xc0) * 64);
        uint2 u1 = *(const uint2*)(xc + (yc0 * Ww + xc1) * 64);
        uint2 u2 = *(const uint2*)(xc + (yc1 * Ww + xc0) * 64);
        uint2 u3 = *(const uint2*)(xc + (yc1 * Ww + xc1) * 64);

        float a0 = 0.f, a1 = 0.f, a2 = 0.f, a3 = 0.f;
        const uint2* us[4] = { &u0, &u1, &u2, &u3 };
        const float  ws[4] = { w4.x, w4.y, w4.z, w4.w };
#pragma unroll
        for (int tap = 0; tap < 4; tap++) {
            uint2 u = *us[tap];
            float w = ws[tap];
            float2 f0 = __half22float2(*(__half2*)&u.x);
            float2 f1 = __half22float2(*(__half2*)&u.y);
            a0 = fmaf(w, f0.x, a0); a1 = fmaf(w, f0.y, a1);
            a2 = fmaf(w, f1.x, a2); a3 = fmaf(w, f1.y, a3);
        }
        __half2 hv[2];
        hv[0] = __floats2half2_rn(a0, a1);
        hv[1] = __floats2half2_rn(a2, a3);
        *(uint2*)&v_sm2[p * VROW + lane * 2] = *(uint2*)hv;
    }
    __syncthreads();

    // ---- Stage 1.5: per-point channel avg / max (1 thread per point) -------
    if (t < NP) {
        const __half2* row = &v_sm2[t * VROW];
        float sum = 0.f, mx = -3.0e38f;
#pragma unroll
        for (int k = 0; k < 8; k++) {
            uint4 u = *(const uint4*)(row + k * 4);
            float2 f0 = __half22float2(*(__half2*)&u.x);
            float2 f1 = __half22float2(*(__half2*)&u.y);
            float2 f2 = __half22float2(*(__half2*)&u.z);
            float2 f3 = __half22float2(*(__half2*)&u.w);
            sum += (f0.x + f0.y) + (f1.x + f1.y) + (f2.x + f2.y) + (f3.x + f3.y);
            mx = fmaxf(mx, fmaxf(fmaxf(f0.x, f0.y), fmaxf(f1.x, f1.y)));
            mx = fmaxf(mx, fmaxf(fmaxf(f2.x, f2.y), fmaxf(f3.x, f3.y)));
        }
        savg[t] = sum * (1.0f / 64.0f);
        smax_[t] = mx;
    }
    __syncthreads();

    // ---- Stage 2: spatial attention gates ----------------------------------
    if (t < TL * 3 * 3) {
        int ra = t / 3, kw = t - ra * 3;   // interior row ra -> v-row ra+1
        float acc = __ldg(sa_b);
#pragma unroll
        for (int kh = 0; kh < 3; kh++) {
            int rr = ra + kh;
#pragma unroll
            for (int k2 = 0; k2 < 3; k2++) {
                int cc = kw + k2 - 1;
                if (cc >= 0 && cc < 3) {
                    int p = rr * 3 + cc;
                    acc += __ldg(&sa_w[kh * 3 + k2])     * savg[p]
                         + __ldg(&sa_w[9 + kh * 3 + k2]) * smax_[p];
                }
            }
        }
        m_att[t] = 1.0f + 1.0f / (1.0f + __expf(-acc));
    }
    __syncthreads();

    // ---- Stage 3: depthwise 3x3 -> g_z (fp16, coalesced) -------------------
    {
        int c2 = t & 31;           // half2 channel pair (2 channels)
        int lg = t >> 5;           // 0..7
        int cA = 2 * c2, cB = 2 * c2 + 1;
        float dwA[9], dwB[9];
#pragma unroll
        for (int k = 0; k < 9; k++) { dwA[k] = dw_sm[cA * 9 + k]; dwB[k] = dw_sm[cB * 9 + k]; }
        float dbA = __ldg(&dw_b[cA]), dbB = __ldg(&dw_b[cB]);
#pragma unroll
        for (int li = 0; li < 2; li++) {
            int l = lg + li * 8;
            float a0 = dbA, a1 = dbB;
#pragma unroll
            for (int kh = 0; kh < 3; kh++)
#pragma unroll
                for (int kw = 0; kw < 3; kw++) {
                    int ra = 3 * l + kh;
                    float g = m_att[ra * 3 + kw];
                    float2 v = __half22float2(v_sm2[((ra + 1) * 3 + kw) * VROW + c2]);
                    a0 = fmaf(dwA[kh * 3 + kw] * g, v.x, a0);
                    a1 = fmaf(dwB[kh * 3 + kw] * g, v.y, a1);
                }
            *(__half2*)&g_z[((size_t)b * LOUT + l0 + l) * 64 + cA] =
                __floats2half2_rn(a0, a1);
        }
    }
}

// ---------------------------------------------------------------------------
// Kernel 3: pointwise GEMM on tensor cores (wmma m16n16k16, fp16 in, fp32 acc)
// out[o, l] = sum_c pw[o,c] * z[l,c] + pb[o].
// Block tile: 64o x 128l. 8 warps: warp w -> m-tile (w&3), n-group (w>>2).
// grid: (Bsz*LOUT/LTI), block 256.
// ---------------------------------------------------------------------------
__global__ __launch_bounds__(256) void pw_k(
    const float* __restrict__ pw_w, const float* __restrict__ pw_b,
    float* __restrict__ out)
{
    __shared__ __align__(16) __half As[64][72];    // pw [o][c]
    __shared__ __align__(16) __half Bs[LTI][72];   // z  [l][c]
    __shared__ float biasT[64][16];                // bias rows (const per row)

    const int t   = threadIdx.x;
    const int bl0 = blockIdx.x * LTI;
    const int b   = bl0 / LOUT;
    const int lbase = bl0 - b * LOUT;

    // Stage A: pw fp32 -> fp16 [o][c]
    for (int i = t * 4; i < 4096; i += 1024) {
        float4 v = *(const float4*)&pw_w[i];
        int o = i >> 6, c = i & 63;
        __half2 h0 = __floats2half2_rn(v.x, v.y);
        __half2 h1 = __floats2half2_rn(v.z, v.w);
        uint2 u; u.x = *(unsigned*)&h0; u.y = *(unsigned*)&h1;
        *(uint2*)&As[o][c] = u;
    }
    // Stage bias tile
    if (t < 64) {
        float pb = __ldg(&pw_b[t]);
#pragma unroll
        for (int j = 0; j < 16; j++) biasT[t][j] = pb;
    }
    // Stage B: z tile [l][c] fp16
    {
        const __half* zg = g_z + (size_t)bl0 * 64;
        for (int i = t * 8; i < LTI * 64; i += 2048) {
            uint4 u = *(const uint4*)&zg[i];
            int l = i >> 6, c = i & 63;
            *(uint4*)&Bs[l][c] = u;
        }
    }
    __syncthreads();

    const int wid = t >> 5;
    const int m   = (wid & 3) * 16;      // o-tile base
    const int ng  = (wid >> 2) * 64;     // n-group base (4 n-tiles of 16)

    wmma::fragment<wmma::accumulator, 16, 16, 16, float> acc[4];
#pragma unroll
    for (int j = 0; j < 4; j++)
        wmma::load_matrix_sync(acc[j], &biasT[m][0], 16, wmma::mem_row_major);

#pragma unroll
    for (int k = 0; k < 64; k += 16) {
        wmma::fragment<wmma::matrix_a, 16, 16, 16, __half, wmma::row_major> af;
        wmma::load_matrix_sync(af, &As[m][k], 72);
#pragma unroll
        for (int j = 0; j < 4; j++) {
            wmma::fragment<wmma::matrix_b, 16, 16, 16, __half, wmma::col_major> bf;
            wmma::load_matrix_sync(bf, &Bs[ng + j * 16][k], 72);
            wmma::mma_sync(acc[j], af, bf, acc[j]);
        }
    }

#pragma unroll
    for (int j = 0; j < 4; j++) {
        float* dst = &out[((size_t)(b * 64 + m)) * LOUT + lbase + ng + j * 16];
        wmma::store_matrix_sync(dst, acc[j], LOUT, wmma::mem_row_major);
    }
}

// ---------------------------------------------------------------------------
extern "C" void kernel_launch(void* const* d_in, const int* in_sizes, int n_in,
                              void* d_out, int out_size) {
    (void)in_sizes; (void)n_in; (void)out_size;
    const float* x    = (const float*)d_in[0];
    const float* grid = (const float*)d_in[1];
    const float* sa_w = (const float*)d_in[2];
    const float* sa_b = (const float*)d_in[3];
    const float* dw_w = (const float*)d_in[4];
    const float* dw_b = (const float*)d_in[5];
    const float* pw_w = (const float*)d_in[6];
    const float* pw_b = (const float*)d_in[7];
    float* out = (float*)d_out;

    transpose_k<<<Bsz * Hh, 256>>>(x);

    dim3 sg(LOUT / TL, Bsz);
    sample_k<<<sg, 256>>>(grid, sa_w, sa_b, dw_w, dw_b);

    pw_k<<<(Bsz * LOUT) / LTI, 256>>>(pw_w, pw_b, out);
}

// round 17
// speedup vs baseline: 1.0908x; 1.0908x over previous
#include <cuda_runtime.h>
#include <cuda_fp16.h>
#include <mma.h>
using namespace nvcuda;

// Problem constants
#define Bsz  2
#define Cc   64
#define Hh   128
#define Ww   256
#define HG   122880          // grid rows = L*KH
#define LOUT 40960           // output rows after stride-3 depthwise
#define TL   16              // output rows per block (sampler)
#define NR   (3*TL + 2)      // local sampled rows incl. +/-1 halo  (50)
#define NP   (NR * 3)        // local sampled points (150)
#define VROW 36              // v_sm2 row pitch in half2 (144B)
#define LTI  128             // pw_k l-tile

__device__ __half g_xT[Bsz * Hh * Ww * Cc];        // x as [B,H,W,C] fp16
__device__ __half g_z[Bsz * LOUT * Cc];            // depthwise output [b*l][c] fp16

// ---------------------------------------------------------------------------
// Kernel 1: NCHW fp32 -> NHWC fp16 transpose.
// One block per (b, h, 64-wide w segment): 1024 blocks, coalesced both sides.
// ---------------------------------------------------------------------------
__global__ __launch_bounds__(256) void transpose_k(const float* __restrict__ x) {
    __shared__ __half s2[64][72];      // [w][c], pitch 72 halves (144B)
    const int blk = blockIdx.x;
    const int w0  = (blk & 3) * 64;    // w segment
    const int bh  = blk >> 2;          // b*128 + h
    const int b   = bh >> 7;
    const int h   = bh & 127;
    const int t   = threadIdx.x;

    // Load: 4 passes over c (16 c per pass); each thread one float4 along w.
    {
        const int w4 = (t & 15) * 4;          // w within segment
        const int cb = t >> 4;                // 0..15
        const float* __restrict__ xp =
            x + (((size_t)(b * Cc) * Hh + h) * Ww) + w0 + w4;
#pragma unroll
        for (int j = 0; j < 4; j++) {
            int c = cb + j * 16;
            float4 v = *(const float4*)(xp + (size_t)c * (Hh * Ww));
            s2[w4 + 0][c] = __float2half_rn(v.x);
            s2[w4 + 1][c] = __float2half_rn(v.y);
            s2[w4 + 2][c] = __float2half_rn(v.z);
            s2[w4 + 3][c] = __float2half_rn(v.w);
        }
    }
    __syncthreads();

    // Store: thread t writes 32B of row w = t>>2; warp = 8 rows x 128B lines.
    {
        const int w  = t >> 2;
        const int cq = (t & 3) * 16;          // halves
        uint4* dst = (uint4*)&g_xT[((size_t)bh * Ww + w0 + w) * Cc + cq];
        const uint4* src = (const uint4*)&s2[w][cq];
        dst[0] = src[0];
        dst[1] = src[1];
    }
}

// ---------------------------------------------------------------------------
// Kernel 2: grid_sample + spatial attention + depthwise(s=3) -> g_z (fp16)
// grid: (LOUT/TL, B), block 256. Branch-free clamped gather, 8 lanes/point.
// (R14-proven configuration)
// ---------------------------------------------------------------------------
__global__ __launch_bounds__(256) void sample_k(
    const float* __restrict__ grid,
    const float* __restrict__ sa_w, const float* __restrict__ sa_b,
    const float* __restrict__ dw_w, const float* __restrict__ dw_b)
{
    __shared__ __align__(16) __half2 v_sm2[NP * VROW]; // 21600 B sampled vecs
    __shared__ __align__(16) float4 cw_sm[NP];         // per-tap weights (0 if OOB)
    __shared__ unsigned cxy_sm[NP];                    // packed clamped coords
    __shared__ float savg[NP];
    __shared__ float smax_[NP];
    __shared__ float m_att[TL * 3 * 3];                // (1 + sigmoid) gates
    __shared__ float dw_sm[64 * 9];

    const int t  = threadIdx.x;
    const int b  = blockIdx.y;
    const int l0 = blockIdx.x * TL;
    const __half* __restrict__ xb = g_xT + (size_t)b * (Hh * Ww * Cc);

    // ---- Stage 0: dw weights + per-point coordinate precompute -------------
    for (int i = t; i < 576; i += 256)
        dw_sm[i] = dw_w[i];

    if (t < NP) {
        float4 w4 = make_float4(0.f, 0.f, 0.f, 0.f);
        int xc0 = 0, xc1 = 0, yc0 = 0, yc1 = 0;
        int gidx = (3 * l0 - 1) * 3 + t;              // linear grid point index
        if (gidx >= 0 && gidx < HG * 3) {
            float2 g2 = __ldg((const float2*)grid + gidx);
            float gx = (g2.x + 1.0f) * 128.0f - 0.5f;   // W/2
            float gy = (g2.y + 1.0f) * 64.0f  - 0.5f;   // H/2
            float x0f = floorf(gx), y0f = floorf(gy);
            float wx = gx - x0f, wy = gy - y0f;
            int x0 = (int)x0f, y0 = (int)y0f;
            float vx0 = ((unsigned)x0       < (unsigned)Ww) ? 1.f : 0.f;
            float vx1 = ((unsigned)(x0 + 1) < (unsigned)Ww) ? 1.f : 0.f;
            float vy0 = ((unsigned)y0       < (unsigned)Hh) ? 1.f : 0.f;
            float vy1 = ((unsigned)(y0 + 1) < (unsigned)Hh) ? 1.f : 0.f;
            w4.x = (1.f - wx) * (1.f - wy) * vx0 * vy0;  // w00
            w4.y = wx * (1.f - wy)         * vx1 * vy0;  // w10
            w4.z = (1.f - wx) * wy         * vx0 * vy1;  // w01
            w4.w = wx * wy                 * vx1 * vy1;  // w11
            xc0 = min(max(x0, 0), Ww - 1);
            xc1 = min(max(x0 + 1, 0), Ww - 1);
            yc0 = min(max(y0, 0), Hh - 1);
            yc1 = min(max(y0 + 1, 0), Hh - 1);
        }
        cw_sm[t] = w4;
        cxy_sm[t] = (unsigned)xc0 | ((unsigned)xc1 << 8)
                  | ((unsigned)yc0 << 16) | ((unsigned)yc1 << 24);
    }
    __syncthreads();

    // ---- Stage 1: branch-free bilinear gather, 8 lanes/pt, 8 ch/lane -------
    const int grp  = t >> 3;      // 0..31
    const int lane = t & 7;
    const int co   = lane * 8;    // channel offset (halves)
    const __half* __restrict__ xc = xb + co;

    for (int p = grp; p < NP; p += 32) {
        float4 w4 = cw_sm[p];
        unsigned pk = cxy_sm[p];
        int xc0 = pk & 255, xc1 = (pk >> 8) & 255;
        int yc0 = (pk >> 16) & 255, yc1 = pk >> 24;
        uint4 u0 = *(const uint4*)(xc + (yc0 * Ww + xc0) * 64);
        uint4 u1 = *(const uint4*)(xc + (yc0 * Ww + xc1) * 64);
        uint4 u2 = *(const uint4*)(xc + (yc1 * Ww + xc0) * 64);
        uint4 u3 = *(const uint4*)(xc + (yc1 * Ww + xc1) * 64);

        float acc[8];
#pragma unroll
        for (int k = 0; k < 8; k++) acc[k] = 0.f;
        const uint4* us[4] = { &u0, &u1, &u2, &u3 };
        const float  ws[4] = { w4.x, w4.y, w4.z, w4.w };
#pragma unroll
        for (int tap = 0; tap < 4; tap++) {
            uint4 u = *us[tap];
            float w = ws[tap];
            float2 f0 = __half22float2(*(__half2*)&u.x);
            float2 f1 = __half22float2(*(__half2*)&u.y);
            float2 f2 = __half22float2(*(__half2*)&u.z);
            float2 f3 = __half22float2(*(__half2*)&u.w);
            acc[0] = fmaf(w, f0.x, acc[0]); acc[1] = fmaf(w, f0.y, acc[1]);
            acc[2] = fmaf(w, f1.x, acc[2]); acc[3] = fmaf(w, f1.y, acc[3]);
            acc[4] = fmaf(w, f2.x, acc[4]); acc[5] = fmaf(w, f2.y, acc[5]);
            acc[6] = fmaf(w, f3.x, acc[6]); acc[7] = fmaf(w, f3.y, acc[7]);
        }
        __half2 hv[4];
#pragma unroll
        for (int k = 0; k < 4; k++)
            hv[k] = __floats2half2_rn(acc[2*k], acc[2*k+1]);
        *(uint4*)&v_sm2[p * VROW + lane * 4] = *(uint4*)hv;
    }
    __syncthreads();

    // ---- Stage 1.5: per-point channel avg / max (1 thread per point) -------
    if (t < NP) {
        const __half2* row = &v_sm2[t * VROW];
        float sum = 0.f, mx = -3.0e38f;
#pragma unroll
        for (int k = 0; k < 8; k++) {
            uint4 u = *(const uint4*)(row + k * 4);
            float2 f0 = __half22float2(*(__half2*)&u.x);
            float2 f1 = __half22float2(*(__half2*)&u.y);
            float2 f2 = __half22float2(*(__half2*)&u.z);
            float2 f3 = __half22float2(*(__half2*)&u.w);
            sum += (f0.x + f0.y) + (f1.x + f1.y) + (f2.x + f2.y) + (f3.x + f3.y);
            mx = fmaxf(mx, fmaxf(fmaxf(f0.x, f0.y), fmaxf(f1.x, f1.y)));
            mx = fmaxf(mx, fmaxf(fmaxf(f2.x, f2.y), fmaxf(f3.x, f3.y)));
        }
        savg[t] = sum * (1.0f / 64.0f);
        smax_[t] = mx;
    }
    __syncthreads();

    // ---- Stage 2: spatial attention gates ----------------------------------
    if (t < TL * 3 * 3) {
        int ra = t / 3, kw = t - ra * 3;   // interior row ra -> v-row ra+1
        float acc = __ldg(sa_b);
#pragma unroll
        for (int kh = 0; kh < 3; kh++) {
            int rr = ra + kh;
#pragma unroll
            for (int k2 = 0; k2 < 3; k2++) {
                int cc = kw + k2 - 1;
                if (cc >= 0 && cc < 3) {
                    int p = rr * 3 + cc;
                    acc += __ldg(&sa_w[kh * 3 + k2])     * savg[p]
                         + __ldg(&sa_w[9 + kh * 3 + k2]) * smax_[p];
                }
            }
        }
        m_att[t] = 1.0f + 1.0f / (1.0f + __expf(-acc));
    }
    __syncthreads();

    // ---- Stage 3: depthwise 3x3 -> g_z (fp16, coalesced) -------------------
    {
        int c2 = t & 31;           // half2 channel pair (2 channels)
        int lg = t >> 5;           // 0..7
        int cA = 2 * c2, cB = 2 * c2 + 1;
        float dwA[9], dwB[9];
#pragma unroll
        for (int k = 0; k < 9; k++) { dwA[k] = dw_sm[cA * 9 + k]; dwB[k] = dw_sm[cB * 9 + k]; }
        float dbA = __ldg(&dw_b[cA]), dbB = __ldg(&dw_b[cB]);
#pragma unroll
        for (int li = 0; li < 2; li++) {
            int l = lg + li * 8;
            float a0 = dbA, a1 = dbB;
#pragma unroll
            for (int kh = 0; kh < 3; kh++)
#pragma unroll
                for (int kw = 0; kw < 3; kw++) {
                    int ra = 3 * l + kh;
                    float g = m_att[ra * 3 + kw];
                    float2 v = __half22float2(v_sm2[((ra + 1) * 3 + kw) * VROW + c2]);
                    a0 = fmaf(dwA[kh * 3 + kw] * g, v.x, a0);
                    a1 = fmaf(dwB[kh * 3 + kw] * g, v.y, a1);
                }
            *(__half2*)&g_z[((size_t)b * LOUT + l0 + l) * 64 + cA] =
                __floats2half2_rn(a0, a1);
        }
    }
}

// ---------------------------------------------------------------------------
// Kernel 3: pointwise GEMM on tensor cores (wmma m16n16k16, fp16 in, fp32 acc)
// out[o, l] = sum_c pw[o,c] * z[l,c] + pb[o].
// Block tile: 64o x 128l. 8 warps: warp w -> m-tile (w&3), n-group (w>>2).
// grid: (Bsz*LOUT/LTI), block 256.
// ---------------------------------------------------------------------------
__global__ __launch_bounds__(256) void pw_k(
    const float* __restrict__ pw_w, const float* __restrict__ pw_b,
    float* __restrict__ out)
{
    __shared__ __align__(16) __half As[64][72];    // pw [o][c]
    __shared__ __align__(16) __half Bs[LTI][72];   // z  [l][c]
    __shared__ float biasT[64][16];                // bias rows (const per row)

    const int t   = threadIdx.x;
    const int bl0 = blockIdx.x * LTI;
    const int b   = bl0 / LOUT;
    const int lbase = bl0 - b * LOUT;

    // Stage A: pw fp32 -> fp16 [o][c]
    for (int i = t * 4; i < 4096; i += 1024) {
        float4 v = *(const float4*)&pw_w[i];
        int o = i >> 6, c = i & 63;
        __half2 h0 = __floats2half2_rn(v.x, v.y);
        __half2 h1 = __floats2half2_rn(v.z, v.w);
        uint2 u; u.x = *(unsigned*)&h0; u.y = *(unsigned*)&h1;
        *(uint2*)&As[o][c] = u;
    }
    // Stage bias tile
    if (t < 64) {
        float pb = __ldg(&pw_b[t]);
#pragma unroll
        for (int j = 0; j < 16; j++) biasT[t][j] = pb;
    }
    // Stage B: z tile [l][c] fp16
    {
        const __half* zg = g_z + (size_t)bl0 * 64;
        for (int i = t * 8; i < LTI * 64; i += 2048) {
            uint4 u = *(const uint4*)&zg[i];
            int l = i >> 6, c = i & 63;
            *(uint4*)&Bs[l][c] = u;
        }
    }
    __syncthreads();

    const int wid = t >> 5;
    const int m   = (wid & 3) * 16;      // o-tile base
    const int ng  = (wid >> 2) * 64;     // n-group base (4 n-tiles of 16)

    wmma::fragment<wmma::accumulator, 16, 16, 16, float> acc[4];
#pragma unroll
    for (int j = 0; j < 4; j++)
        wmma::load_matrix_sync(acc[j], &biasT[m][0], 16, wmma::mem_row_major);

#pragma unroll
    for (int k = 0; k < 64; k += 16) {
        wmma::fragment<wmma::matrix_a, 16, 16, 16, __half, wmma::row_major> af;
        wmma::load_matrix_sync(af, &As[m][k], 72);
#pragma unroll
        for (int j = 0; j < 4; j++) {
            wmma::fragment<wmma::matrix_b, 16, 16, 16, __half, wmma::col_major> bf;
            wmma::load_matrix_sync(bf, &Bs[ng + j * 16][k], 72);
            wmma::mma_sync(acc[j], af, bf, acc[j]);
        }
    }

#pragma unroll
    for (int j = 0; j < 4; j++) {
        float* dst = &out[((size_t)(b * 64 + m)) * LOUT + lbase + ng + j * 16];
        wmma::store_matrix_sync(dst, acc[j], LOUT, wmma::mem_row_major);
    }
}

// ---------------------------------------------------------------------------
extern "C" void kernel_launch(void* const* d_in, const int* in_sizes, int n_in,
                              void* d_out, int out_size) {
    (void)in_sizes; (void)n_in; (void)out_size;
    const float* x    = (const float*)d_in[0];
    const float* grid = (const float*)d_in[1];
    const float* sa_w = (const float*)d_in[2];
    const float* sa_b = (const float*)d_in[3];
    const float* dw_w = (const float*)d_in[4];
    const float* dw_b = (const float*)d_in[5];
    const float* pw_w = (const float*)d_in[6];
    const float* pw_b = (const float*)d_in[7];
    float* out = (float*)d_out;

    transpose_k<<<Bsz * Hh * 4, 256>>>(x);

    dim3 sg(LOUT / TL, Bsz);
    sample_k<<<sg, 256>>>(grid, sa_w, sa_b, dw_w, dw_b);

    pw_k<<<(Bsz * LOUT) / LTI, 256>>>(pw_w, pw_b, out);
}